// round 1
// baseline (speedup 1.0000x reference)
#include <cuda_runtime.h>
#include <math.h>

// Problem dims
#define NBS 65536          // B*S = B*P = 64*1024 rows
#define DIN 50
#define DD  300
#define BB  64
#define SS  1024
#define PP  1024
#define OUTD 1024

// ---------------- scratch (static device arrays; no runtime alloc) -------------
__device__ float g_token[(size_t)NBS * DD];        // token (post-LN), later filter_token (in-place add)
__device__ float g_past_token[(size_t)NBS * DD];
__device__ float g_expose[(size_t)NBS * DD];
__device__ float g_past_vector[(size_t)NBS * DD];
__device__ float g_past_state[(size_t)NBS * DD];
__device__ float g_pre_state[(size_t)NBS * DD];
__device__ float g_h[(size_t)NBS * DD];
__device__ float g_gate[(size_t)BB * SS * PP];     // reused: past_gate, then expose_gate

// ---------------- projection: C[M,300] = act(A[M,50] @ W[50,300] + bias) -------
// blockDim = 300 (one thread per output column), 32 rows per block.
__global__ void proj_kernel(const float* __restrict__ A, const float* __restrict__ W,
                            const float* __restrict__ bias, float* __restrict__ C,
                            int act)
{
    __shared__ float sA[32][DIN];
    const int j    = threadIdx.x;            // 0..299
    const int row0 = blockIdx.x * 32;

    for (int i = threadIdx.x; i < 32 * DIN; i += blockDim.x)
        sA[i / DIN][i % DIN] = A[(size_t)(row0 + i / DIN) * DIN + (i % DIN)];
    __syncthreads();

    float w[DIN];
#pragma unroll
    for (int k = 0; k < DIN; k++) w[k] = W[k * DD + j];
    const float b = bias ? bias[j] : 0.0f;

#pragma unroll 4
    for (int r = 0; r < 32; r++) {
        float acc = b;
#pragma unroll
        for (int k = 0; k < DIN; k++) acc += sA[r][k] * w[k];
        if (act) acc = tanhf(acc);
        C[(size_t)(row0 + r) * DD + j] = acc;
    }
}

// ---------------- LayerNorm over last dim (300), in place ---------------------
__global__ void ln_kernel(float* __restrict__ T,
                          const float* __restrict__ g, const float* __restrict__ b)
{
    const int row  = blockIdx.x * (blockDim.x >> 5) + (threadIdx.x >> 5);
    const int lane = threadIdx.x & 31;
    float* p = T + (size_t)row * DD;

    float v[10];
    float s = 0.0f;
#pragma unroll
    for (int i = 0; i < 10; i++) {
        int j = lane + i * 32;
        v[i] = (j < DD) ? p[j] : 0.0f;
        s += v[i];
    }
#pragma unroll
    for (int o = 16; o; o >>= 1) s += __shfl_xor_sync(0xffffffffu, s, o);
    const float mu = s * (1.0f / DD);

    float q = 0.0f;
#pragma unroll
    for (int i = 0; i < 10; i++) {
        int j = lane + i * 32;
        if (j < DD) { float d = v[i] - mu; q += d * d; }
    }
#pragma unroll
    for (int o = 16; o; o >>= 1) q += __shfl_xor_sync(0xffffffffu, q, o);
    const float inv = rsqrtf(q * (1.0f / DD) + 1e-6f);

#pragma unroll
    for (int i = 0; i < 10; i++) {
        int j = lane + i * 32;
        if (j < DD) p[j] = g[j] * (v[i] - mu) * inv + b[j];
    }
}

// ---------------- generic batched SGEMM: 128x128x8 tiles, 256 threads ---------
// A: [M,K] row-major. B: TB ? [N,K] (C = A*B^T) : [K,N] (C = A*B). Row-major C [M,N].
// MODE: 0 none, 1 sigmoid, 2 C = acc + aux[r,c] (elementwise), 3 relu(acc+aux[c]), 4 acc+aux[c]
// Requires K%4==0, N%4==0, M%128==0 (true for all call sites).
template <bool TB, int MODE>
__global__ void __launch_bounds__(256, 2)
sgemm_kernel(const float* __restrict__ A, const float* __restrict__ Bm,
             float* __restrict__ C, const float* __restrict__ aux,
             int M, int N, int K,
             long long strA, long long strB, long long strC, long long strAux)
{
    __shared__ float As[8][128];
    __shared__ float Bs[8][128];

    const float* Ab = A  + (size_t)blockIdx.z * strA;
    const float* Bb = Bm + (size_t)blockIdx.z * strB;
    float*       Cb = C  + (size_t)blockIdx.z * strC;
    const float* Xb = aux ? aux + (size_t)blockIdx.z * strAux : (const float*)0;

    const int tid = threadIdx.x;
    const int tx  = tid & 15;        // col group
    const int ty  = tid >> 4;        // row group
    const int rowTile = blockIdx.y * 128;
    const int colTile = blockIdx.x * 128;

    // loader indices
    const int la_m = tid >> 1;           // 0..127
    const int la_k = (tid & 1) * 4;      // 0 or 4
    const int lb_k = tid >> 5;           // 0..7  (NN)
    const int lb_n = (tid & 31) * 4;     // 0..124 (NN)

    float acc[8][8];
#pragma unroll
    for (int i = 0; i < 8; i++)
#pragma unroll
        for (int j = 0; j < 8; j++) acc[i][j] = 0.0f;

    for (int k0 = 0; k0 < K; k0 += 8) {
        float4 av = make_float4(0.f, 0.f, 0.f, 0.f);
        float4 bv = make_float4(0.f, 0.f, 0.f, 0.f);

        if (k0 + la_k < K)
            av = *(const float4*)&Ab[(size_t)(rowTile + la_m) * K + k0 + la_k];

        if (TB) {
            if ((k0 + la_k < K) && (colTile + la_m < N))
                bv = *(const float4*)&Bb[(size_t)(colTile + la_m) * K + k0 + la_k];
        } else {
            if ((k0 + lb_k < K) && (colTile + lb_n < N))
                bv = *(const float4*)&Bb[(size_t)(k0 + lb_k) * N + colTile + lb_n];
        }

        __syncthreads();   // previous iter compute done before overwrite

        As[la_k + 0][la_m] = av.x;
        As[la_k + 1][la_m] = av.y;
        As[la_k + 2][la_m] = av.z;
        As[la_k + 3][la_m] = av.w;
        if (TB) {
            Bs[la_k + 0][la_m] = bv.x;
            Bs[la_k + 1][la_m] = bv.y;
            Bs[la_k + 2][la_m] = bv.z;
            Bs[la_k + 3][la_m] = bv.w;
        } else {
            *(float4*)&Bs[lb_k][lb_n] = bv;
        }
        __syncthreads();

#pragma unroll
        for (int kk = 0; kk < 8; kk++) {
            float af[8], bf[8];
            *(float4*)&af[0] = *(const float4*)&As[kk][ty * 4];
            *(float4*)&af[4] = *(const float4*)&As[kk][64 + ty * 4];
            *(float4*)&bf[0] = *(const float4*)&Bs[kk][tx * 4];
            *(float4*)&bf[4] = *(const float4*)&Bs[kk][64 + tx * 4];
#pragma unroll
            for (int i = 0; i < 8; i++)
#pragma unroll
                for (int j = 0; j < 8; j++)
                    acc[i][j] += af[i] * bf[j];
        }
    }

    // epilogue: two float4 stores per fragment row
#pragma unroll
    for (int i = 0; i < 8; i++) {
        const int r = rowTile + ((i < 4) ? (ty * 4 + i) : (60 + ty * 4 + i));
        if (r >= M) continue;
#pragma unroll
        for (int h = 0; h < 2; h++) {
            const int c = colTile + h * 64 + tx * 4;
            if (c >= N) continue;
            float v0 = acc[i][h * 4 + 0];
            float v1 = acc[i][h * 4 + 1];
            float v2 = acc[i][h * 4 + 2];
            float v3 = acc[i][h * 4 + 3];
            if (MODE == 1) {
                v0 = 1.0f / (1.0f + __expf(-v0));
                v1 = 1.0f / (1.0f + __expf(-v1));
                v2 = 1.0f / (1.0f + __expf(-v2));
                v3 = 1.0f / (1.0f + __expf(-v3));
            } else if (MODE == 2) {
                float4 a4 = *(const float4*)&Xb[(size_t)r * N + c];
                v0 += a4.x; v1 += a4.y; v2 += a4.z; v3 += a4.w;
            } else if (MODE == 3) {
                float4 b4 = *(const float4*)&Xb[c];
                v0 = fmaxf(v0 + b4.x, 0.f);
                v1 = fmaxf(v1 + b4.y, 0.f);
                v2 = fmaxf(v2 + b4.z, 0.f);
                v3 = fmaxf(v3 + b4.w, 0.f);
            } else if (MODE == 4) {
                float4 b4 = *(const float4*)&Xb[c];
                v0 += b4.x; v1 += b4.y; v2 += b4.z; v3 += b4.w;
            }
            *(float4*)&Cb[(size_t)r * N + c] = make_float4(v0, v1, v2, v3);
        }
    }
}

// -------------------------------------------------------------------------------
extern "C" void kernel_launch(void* const* d_in, const int* in_sizes, int n_in,
                              void* d_out, int out_size)
{
    (void)in_sizes; (void)n_in; (void)out_size;

    const float* x    = (const float*)d_in[0];   // [64,1024,50]
    const float* ME   = (const float*)d_in[1];   // [50,300]
    const float* past = (const float*)d_in[2];   // [64,1024,50]
    const float* w_pt = (const float*)d_in[3];
    const float* b_pt = (const float*)d_in[4];
    const float* w_pg = (const float*)d_in[5];
    const float* b_pg = (const float*)d_in[6];
    const float* w_ps = (const float*)d_in[7];
    const float* b_ps = (const float*)d_in[8];
    const float* w_ex = (const float*)d_in[9];
    const float* b_ex = (const float*)d_in[10];
    const float* ln_g = (const float*)d_in[11];
    const float* ln_b = (const float*)d_in[12];
    const float* W1   = (const float*)d_in[13];  // [300,300]
    const float* b1   = (const float*)d_in[14];
    const float* W2   = (const float*)d_in[15];  // [300,1024]
    const float* b2   = (const float*)d_in[16];
    float* out = (float*)d_out;                  // [64,1024,1024]

    float *p_token, *p_ptok, *p_exp, *p_pvec, *p_pst, *p_pre, *p_h, *p_gate;
    cudaGetSymbolAddress((void**)&p_token, g_token);
    cudaGetSymbolAddress((void**)&p_ptok,  g_past_token);
    cudaGetSymbolAddress((void**)&p_exp,   g_expose);
    cudaGetSymbolAddress((void**)&p_pvec,  g_past_vector);
    cudaGetSymbolAddress((void**)&p_pst,   g_past_state);
    cudaGetSymbolAddress((void**)&p_pre,   g_pre_state);
    cudaGetSymbolAddress((void**)&p_h,     g_h);
    cudaGetSymbolAddress((void**)&p_gate,  g_gate);

    const long long sD  = (long long)SS * DD;      // 307200
    const long long sG  = (long long)SS * PP;      // 1048576

    // Stage A: projections (K = 50)
    proj_kernel<<<NBS / 32, 300>>>(x,    ME,   (const float*)0, p_token, 0);
    proj_kernel<<<NBS / 32, 300>>>(x,    w_pt, b_pt, p_ptok, 1);
    proj_kernel<<<NBS / 32, 300>>>(x,    w_ex, b_ex, p_exp,  1);
    proj_kernel<<<NBS / 32, 300>>>(past, w_pg, b_pg, p_pvec, 1);
    proj_kernel<<<NBS / 32, 300>>>(past, w_ps, b_ps, p_pst,  1);
    ln_kernel<<<NBS / 8, 256>>>(p_token, ln_g, ln_b);

    // G1: past_gate = sigmoid(past_token @ past_vector^T)   [b,1024,1024]
    sgemm_kernel<true, 1><<<dim3(8, 8, BB), 256>>>(
        p_ptok, p_pvec, p_gate, (const float*)0, SS, PP, DD, sD, sD, sG, 0);

    // G2: pre_state = past_gate @ past_state                [b,1024,300]
    sgemm_kernel<false, 0><<<dim3(3, 8, BB), 256>>>(
        p_gate, p_pst, p_pre, (const float*)0, SS, DD, PP, sG, sD, sD, 0);

    // G3: expose_gate = sigmoid(expose_vector @ pre_state^T) [b,1024,1024]
    sgemm_kernel<true, 1><<<dim3(8, 8, BB), 256>>>(
        p_exp, p_pre, p_gate, (const float*)0, SS, SS, DD, sD, sD, sG, 0);

    // G4: filter_token = token + expose_gate @ pre_state   (in-place into g_token)
    sgemm_kernel<false, 2><<<dim3(3, 8, BB), 256>>>(
        p_gate, p_pre, p_token, p_token, SS, DD, SS, sG, sD, sD, sD);

    // G5: h = relu(filter_token @ W1 + b1)                  [65536,300]
    sgemm_kernel<false, 3><<<dim3(3, 512, 1), 256>>>(
        p_token, W1, p_h, b1, NBS, DD, DD, 0, 0, 0, 0);

    // G6: out = h @ W2 + b2                                 [65536,1024]
    sgemm_kernel<false, 4><<<dim3(8, 512, 1), 256>>>(
        p_h, W2, out, b2, NBS, OUTD, DD, 0, 0, 0, 0);
}

// round 3
// speedup vs baseline: 1.1752x; 1.1752x over previous
#include <cuda_runtime.h>
#include <cstdint>
#include <math.h>

// ---------------- problem dims ----------------
#define NBS 65536          // 64*1024 rows
#define DIN 50
#define DD  300
#define BB  64
#define SS  1024
#define OUTD 1024

// ---------------- scratch (static device arrays) ----------------
__device__ float g_token[(size_t)NBS * DD];
__device__ float g_ptok [(size_t)NBS * DD];
__device__ float g_expv [(size_t)NBS * DD];
__device__ float g_pvec [(size_t)NBS * DD];
__device__ float g_pst  [(size_t)NBS * DD];
__device__ float g_pstT [(size_t)NBS * DD];
__device__ float g_pre  [(size_t)NBS * DD];
__device__ float g_preT [(size_t)NBS * DD];
__device__ float g_h    [(size_t)NBS * DD];
__device__ float g_gate [(size_t)BB * SS * SS];
__device__ float g_W1t [DD * DD];
__device__ float g_W2t [OUTD * DD];

// ---------------- tf32 helpers ----------------
__device__ __forceinline__ void split1(float v, uint32_t& h, uint32_t& l) {
    asm("cvt.rna.tf32.f32 %0, %1;" : "=r"(h) : "f"(v));
    float r = v - __uint_as_float(h);
    asm("cvt.rna.tf32.f32 %0, %1;" : "=r"(l) : "f"(r));
}
__device__ __forceinline__ void split4(float4 v, uint4& h, uint4& l) {
    split1(v.x, h.x, l.x); split1(v.y, h.y, l.y);
    split1(v.z, h.z, l.z); split1(v.w, h.w, l.w);
}
__device__ __forceinline__ void mma8(float* d, const uint32_t* a, const uint32_t* b) {
    asm volatile("mma.sync.aligned.m16n8k8.row.col.f32.tf32.tf32.f32 "
        "{%0,%1,%2,%3}, {%4,%5,%6,%7}, {%8,%9}, {%0,%1,%2,%3};"
        : "+f"(d[0]), "+f"(d[1]), "+f"(d[2]), "+f"(d[3])
        : "r"(a[0]), "r"(a[1]), "r"(a[2]), "r"(a[3]), "r"(b[0]), "r"(b[1]));
}

// ---------------- tensor-core tf32-split GEMM ----------------
// C[M,N] = epi(A[M,K] @ B[N,K]^T); row-major; batch via blockIdx.z strides.
// EPI: 0 none | 1 sigmoid | 2 +aux[r,c] | 3 relu(+bias) | 4 +bias
// Requires: M % 128 == 0, N even, rows of A and B 16B-aligned (K%4==0).
static constexpr int TSTRIDE = 36;                 // floats per smem row (pad)
static constexpr int TILE_F  = 128 * TSTRIDE;      // 4608 floats per operand tile
static constexpr int STAGE_F = 4 * TILE_F;         // Ah, Al, Bh, Bl
static constexpr uint32_t MG_SMEM = 2 * STAGE_F * 4;   // 147456 bytes

template <int EPI>
__global__ void __launch_bounds__(256, 1)
mgemm(const float* __restrict__ A, const float* __restrict__ Bm,
      float* __restrict__ C, const float* __restrict__ aux,
      int M, int N, int K,
      long long sA, long long sB, long long sC, long long sAux)
{
    extern __shared__ float sm[];
    const int tid = threadIdx.x;
    const int wid = tid >> 5, lane = tid & 31;
    const int g = lane >> 2, tg = lane & 3;
    const int wr = wid >> 2, wc = wid & 3;
    const int rowTile = blockIdx.y * 128;
    const int colTile = blockIdx.x * 128;

    const float* Ab = A + (size_t)blockIdx.z * sA;
    const float* Bb = Bm + (size_t)blockIdx.z * sB;
    float*       Cb = C + (size_t)blockIdx.z * sC;
    const float* Xb = aux ? aux + (size_t)blockIdx.z * sAux : (const float*)0;

    float acc[4][4][4];
#pragma unroll
    for (int i = 0; i < 4; i++)
#pragma unroll
        for (int j = 0; j < 4; j++)
#pragma unroll
            for (int t = 0; t < 4; t++) acc[i][j][t] = 0.0f;

    const int T = (K + 31) >> 5;
    float4 pa[4], pb[4];

    // ---- tile loader (into registers) ----
    auto load_tile = [&](int t) {
        const int k0 = t << 5;
#pragma unroll
        for (int i = 0; i < 4; i++) {
            const int id = tid + i * 256;
            const int row = id >> 3;
            const int k = k0 + (id & 7) * 4;
            const float* ap = Ab + (size_t)(rowTile + row) * K;
            float4 v = make_float4(0.f, 0.f, 0.f, 0.f);
            if (k + 3 < K) v = *(const float4*)(ap + k);
            else {
                if (k + 0 < K) v.x = ap[k + 0];
                if (k + 1 < K) v.y = ap[k + 1];
                if (k + 2 < K) v.z = ap[k + 2];
            }
            pa[i] = v;
            const int n = colTile + row;
            float4 w = make_float4(0.f, 0.f, 0.f, 0.f);
            if (n < N) {
                const float* bp = Bb + (size_t)n * K;
                if (k + 3 < K) w = *(const float4*)(bp + k);
                else {
                    if (k + 0 < K) w.x = bp[k + 0];
                    if (k + 1 < K) w.y = bp[k + 1];
                    if (k + 2 < K) w.z = bp[k + 2];
                }
            }
            pb[i] = w;
        }
    };
    // ---- split + store registers into smem stage ----
    auto store_tile = [&](int stage) {
        float* st = sm + stage * STAGE_F;
#pragma unroll
        for (int i = 0; i < 4; i++) {
            const int id = tid + i * 256;
            const int off = (id >> 3) * TSTRIDE + (id & 7) * 4;
            uint4 h, l;
            split4(pa[i], h, l);
            *(uint4*)(st + off) = h;
            *(uint4*)(st + TILE_F + off) = l;
            split4(pb[i], h, l);
            *(uint4*)(st + 2 * TILE_F + off) = h;
            *(uint4*)(st + 3 * TILE_F + off) = l;
        }
    };

    load_tile(0);
    store_tile(0);
    __syncthreads();

    for (int t = 0; t < T; t++) {
        if (t + 1 < T) load_tile(t + 1);

        const uint32_t* st = (const uint32_t*)(sm + (t & 1) * STAGE_F);
        const uint32_t* Ah = st;
        const uint32_t* Al = st + TILE_F;
        const uint32_t* Bh = st + 2 * TILE_F;
        const uint32_t* Bl = st + 3 * TILE_F;

#pragma unroll
        for (int kk = 0; kk < 4; kk++) {
            const int kt = kk * 8 + tg;
            uint32_t ah[4][4], al[4][4];
#pragma unroll
            for (int mi = 0; mi < 4; mi++) {
                const int r0 = (wr * 64 + mi * 16 + g) * TSTRIDE;
                const int r1 = r0 + 8 * TSTRIDE;
                ah[mi][0] = Ah[r0 + kt];     ah[mi][1] = Ah[r1 + kt];
                ah[mi][2] = Ah[r0 + kt + 4]; ah[mi][3] = Ah[r1 + kt + 4];
                al[mi][0] = Al[r0 + kt];     al[mi][1] = Al[r1 + kt];
                al[mi][2] = Al[r0 + kt + 4]; al[mi][3] = Al[r1 + kt + 4];
            }
            uint32_t bh[4][2], bl[4][2];
#pragma unroll
            for (int nj = 0; nj < 4; nj++) {
                const int n0 = (wc * 32 + nj * 8 + g) * TSTRIDE;
                bh[nj][0] = Bh[n0 + kt]; bh[nj][1] = Bh[n0 + kt + 4];
                bl[nj][0] = Bl[n0 + kt]; bl[nj][1] = Bl[n0 + kt + 4];
            }
#pragma unroll
            for (int mi = 0; mi < 4; mi++)
#pragma unroll
                for (int nj = 0; nj < 4; nj++) {
                    mma8(acc[mi][nj], ah[mi], bh[nj]);
                    mma8(acc[mi][nj], ah[mi], bl[nj]);
                    mma8(acc[mi][nj], al[mi], bh[nj]);
                }
        }

        if (t + 1 < T) store_tile((t + 1) & 1);
        __syncthreads();
    }

    // ---- epilogue ----
#pragma unroll
    for (int mi = 0; mi < 4; mi++) {
#pragma unroll
        for (int nj = 0; nj < 4; nj++) {
            const int c = colTile + wc * 32 + nj * 8 + tg * 2;
            if (c >= N) continue;
#pragma unroll
            for (int half = 0; half < 2; half++) {
                const int r = rowTile + wr * 64 + mi * 16 + g + half * 8;
                float v0 = acc[mi][nj][half * 2 + 0];
                float v1 = acc[mi][nj][half * 2 + 1];
                if (EPI == 1) {
                    v0 = 1.0f / (1.0f + __expf(-v0));
                    v1 = 1.0f / (1.0f + __expf(-v1));
                } else if (EPI == 2) {
                    const float2 x2 = *(const float2*)&Xb[(size_t)r * N + c];
                    v0 += x2.x; v1 += x2.y;
                } else if (EPI == 3) {
                    const float2 b2 = *(const float2*)&Xb[c];
                    v0 = fmaxf(v0 + b2.x, 0.f);
                    v1 = fmaxf(v1 + b2.y, 0.f);
                } else if (EPI == 4) {
                    const float2 b2 = *(const float2*)&Xb[c];
                    v0 += b2.x; v1 += b2.y;
                }
                *(float2*)&Cb[(size_t)r * N + c] = make_float2(v0, v1);
            }
        }
    }
}

// ---------------- projection: C[M,300] = act(A[M,50] @ W[50,300] + bias) -------
__global__ void proj_kernel(const float* __restrict__ A, const float* __restrict__ W,
                            const float* __restrict__ bias, float* __restrict__ C,
                            int act)
{
    __shared__ float sA[32][DIN];
    const int j    = threadIdx.x;            // 0..299
    const int row0 = blockIdx.x * 32;

    for (int i = threadIdx.x; i < 32 * DIN; i += blockDim.x)
        sA[i / DIN][i % DIN] = A[(size_t)(row0 + i / DIN) * DIN + (i % DIN)];
    __syncthreads();

    float w[DIN];
#pragma unroll
    for (int k = 0; k < DIN; k++) w[k] = W[k * DD + j];
    const float b = bias ? bias[j] : 0.0f;

#pragma unroll 4
    for (int r = 0; r < 32; r++) {
        float acc = b;
#pragma unroll
        for (int k = 0; k < DIN; k++) acc += sA[r][k] * w[k];
        if (act) acc = tanhf(acc);
        C[(size_t)(row0 + r) * DD + j] = acc;
    }
}

// ---------------- LayerNorm over last dim (300), in place ---------------------
__global__ void ln_kernel(float* __restrict__ T,
                          const float* __restrict__ g, const float* __restrict__ b)
{
    const int row  = blockIdx.x * (blockDim.x >> 5) + (threadIdx.x >> 5);
    const int lane = threadIdx.x & 31;
    float* p = T + (size_t)row * DD;

    float v[10];
    float s = 0.0f;
#pragma unroll
    for (int i = 0; i < 10; i++) {
        int j = lane + i * 32;
        v[i] = (j < DD) ? p[j] : 0.0f;
        s += v[i];
    }
#pragma unroll
    for (int o = 16; o; o >>= 1) s += __shfl_xor_sync(0xffffffffu, s, o);
    const float mu = s * (1.0f / DD);

    float q = 0.0f;
#pragma unroll
    for (int i = 0; i < 10; i++) {
        int j = lane + i * 32;
        if (j < DD) { float d = v[i] - mu; q += d * d; }
    }
#pragma unroll
    for (int o = 16; o; o >>= 1) q += __shfl_xor_sync(0xffffffffu, q, o);
    const float inv = rsqrtf(q * (1.0f / DD) + 1e-6f);

#pragma unroll
    for (int i = 0; i < 10; i++) {
        int j = lane + i * 32;
        if (j < DD) p[j] = g[j] * (v[i] - mu) * inv + b[j];
    }
}

// ---------------- transpose: out[C,R] = in[R,C]^T, batched via z ----------------
__global__ void transpose_kernel(const float* __restrict__ in, float* __restrict__ out,
                                 int R, int C, long long strIn, long long strOut)
{
    __shared__ float t[32][33];
    const float* ib = in + (size_t)blockIdx.z * strIn;
    float* ob = out + (size_t)blockIdx.z * strOut;
    const int c0 = blockIdx.x * 32, r0 = blockIdx.y * 32;
    const int x = threadIdx.x, y = threadIdx.y;
#pragma unroll
    for (int i = 0; i < 32; i += 8) {
        int r = r0 + y + i, c = c0 + x;
        t[y + i][x] = (r < R && c < C) ? ib[(size_t)r * C + c] : 0.f;
    }
    __syncthreads();
#pragma unroll
    for (int i = 0; i < 32; i += 8) {
        int r = c0 + y + i, c = r0 + x;
        if (r < C && c < R) ob[(size_t)r * R + c] = t[x][y + i];
    }
}

// -------------------------------------------------------------------------------
extern "C" void kernel_launch(void* const* d_in, const int* in_sizes, int n_in,
                              void* d_out, int out_size)
{
    (void)in_sizes; (void)n_in; (void)out_size;

    const float* x    = (const float*)d_in[0];
    const float* ME   = (const float*)d_in[1];
    const float* past = (const float*)d_in[2];
    const float* w_pt = (const float*)d_in[3];
    const float* b_pt = (const float*)d_in[4];
    const float* w_pg = (const float*)d_in[5];
    const float* b_pg = (const float*)d_in[6];
    const float* w_ps = (const float*)d_in[7];
    const float* b_ps = (const float*)d_in[8];
    const float* w_ex = (const float*)d_in[9];
    const float* b_ex = (const float*)d_in[10];
    const float* ln_g = (const float*)d_in[11];
    const float* ln_b = (const float*)d_in[12];
    const float* W1   = (const float*)d_in[13];
    const float* b1   = (const float*)d_in[14];
    const float* W2   = (const float*)d_in[15];
    const float* b2   = (const float*)d_in[16];
    float* out = (float*)d_out;

    float *p_token, *p_ptok, *p_exp, *p_pvec, *p_pst, *p_pstT, *p_pre, *p_preT, *p_h, *p_gate;
    float *p_W1t, *p_W2t;
    cudaGetSymbolAddress((void**)&p_token, g_token);
    cudaGetSymbolAddress((void**)&p_ptok,  g_ptok);
    cudaGetSymbolAddress((void**)&p_exp,   g_expv);
    cudaGetSymbolAddress((void**)&p_pvec,  g_pvec);
    cudaGetSymbolAddress((void**)&p_pst,   g_pst);
    cudaGetSymbolAddress((void**)&p_pstT,  g_pstT);
    cudaGetSymbolAddress((void**)&p_pre,   g_pre);
    cudaGetSymbolAddress((void**)&p_preT,  g_preT);
    cudaGetSymbolAddress((void**)&p_h,     g_h);
    cudaGetSymbolAddress((void**)&p_gate,  g_gate);
    cudaGetSymbolAddress((void**)&p_W1t,   g_W1t);
    cudaGetSymbolAddress((void**)&p_W2t,   g_W2t);

    cudaFuncSetAttribute(mgemm<0>, cudaFuncAttributeMaxDynamicSharedMemorySize, MG_SMEM);
    cudaFuncSetAttribute(mgemm<1>, cudaFuncAttributeMaxDynamicSharedMemorySize, MG_SMEM);
    cudaFuncSetAttribute(mgemm<2>, cudaFuncAttributeMaxDynamicSharedMemorySize, MG_SMEM);
    cudaFuncSetAttribute(mgemm<3>, cudaFuncAttributeMaxDynamicSharedMemorySize, MG_SMEM);
    cudaFuncSetAttribute(mgemm<4>, cudaFuncAttributeMaxDynamicSharedMemorySize, MG_SMEM);

    const long long sD = (long long)SS * DD;   // 307200
    const long long sG = (long long)SS * SS;   // 1048576
    dim3 tpb(32, 8);

    // projections (K = 50, FFMA path)
    proj_kernel<<<NBS / 32, 300>>>(x,    ME,   (const float*)0, p_token, 0);
    proj_kernel<<<NBS / 32, 300>>>(x,    w_pt, b_pt, p_ptok, 1);
    proj_kernel<<<NBS / 32, 300>>>(x,    w_ex, b_ex, p_exp,  1);
    proj_kernel<<<NBS / 32, 300>>>(past, w_pg, b_pg, p_pvec, 1);
    proj_kernel<<<NBS / 32, 300>>>(past, w_ps, b_ps, p_pst,  1);
    ln_kernel<<<NBS / 8, 256>>>(p_token, ln_g, ln_b);

    // weight / activation transposes to K-major B layouts
    transpose_kernel<<<dim3(10, 10, 1), tpb>>>(W1, p_W1t, DD, DD, 0, 0);
    transpose_kernel<<<dim3(32, 10, 1), tpb>>>(W2, p_W2t, DD, OUTD, 0, 0);
    transpose_kernel<<<dim3(10, 32, BB), tpb>>>(p_pst, p_pstT, SS, DD, sD, sD);

    // G1: past_gate = sigmoid(ptok @ pvec^T)              [b,1024,1024]
    mgemm<1><<<dim3(8, 8, BB), 256, MG_SMEM>>>(p_ptok, p_pvec, p_gate, (const float*)0,
                                               SS, SS, DD, sD, sD, sG, 0);
    // G2: pre_state = gate @ past_state  (B = pstT)       [b,1024,300]
    mgemm<0><<<dim3(3, 8, BB), 256, MG_SMEM>>>(p_gate, p_pstT, p_pre, (const float*)0,
                                               SS, DD, SS, sG, sD, sD, 0);
    transpose_kernel<<<dim3(10, 32, BB), tpb>>>(p_pre, p_preT, SS, DD, sD, sD);

    // G3: expose_gate = sigmoid(expose @ pre^T)           [b,1024,1024]
    mgemm<1><<<dim3(8, 8, BB), 256, MG_SMEM>>>(p_exp, p_pre, p_gate, (const float*)0,
                                               SS, SS, DD, sD, sD, sG, 0);
    // G4: filter = token + gate2 @ pre  (in-place)        [b,1024,300]
    mgemm<2><<<dim3(3, 8, BB), 256, MG_SMEM>>>(p_gate, p_preT, p_token, p_token,
                                               SS, DD, SS, sG, sD, sD, sD);
    // G5: h = relu(filter @ W1 + b1)                      [65536,300]
    mgemm<3><<<dim3(3, 512, 1), 256, MG_SMEM>>>(p_token, p_W1t, p_h, b1,
                                                NBS, DD, DD, 0, 0, 0, 0);
    // G6: out = h @ W2 + b2                               [65536,1024]
    mgemm<4><<<dim3(8, 512, 1), 256, MG_SMEM>>>(p_h, p_W2t, out, b2,
                                                NBS, OUTD, DD, 0, 0, 0, 0);
}

// round 4
// speedup vs baseline: 1.6428x; 1.3979x over previous
#include <cuda_runtime.h>
#include <cuda_bf16.h>
#include <cstdint>
#include <math.h>

// ---------------- problem dims ----------------
#define NBS 65536          // 64*1024 rows
#define DIN 50
#define DD  300
#define DP  320            // DD padded to multiple of 32
#define BB  64
#define SS  1024
#define OUTD 1024

typedef __nv_bfloat16 bf16;

// ---------------- scratch (static device arrays) ----------------
__device__ float g_token[(size_t)NBS * DD];
__device__ float g_pst  [(size_t)NBS * DD];
__device__ float g_pre  [(size_t)NBS * DD];

__device__ bf16 g_ptokH[(size_t)NBS * DP];
__device__ bf16 g_ptokL[(size_t)NBS * DP];
__device__ bf16 g_pvecH[(size_t)NBS * DP];
__device__ bf16 g_pvecL[(size_t)NBS * DP];
__device__ bf16 g_expH [(size_t)NBS * DP];
__device__ bf16 g_expL [(size_t)NBS * DP];
__device__ bf16 g_preH [(size_t)NBS * DP];
__device__ bf16 g_preL [(size_t)NBS * DP];
__device__ bf16 g_filtH[(size_t)NBS * DP];
__device__ bf16 g_filtL[(size_t)NBS * DP];
__device__ bf16 g_hH   [(size_t)NBS * DP];
__device__ bf16 g_hL   [(size_t)NBS * DP];
__device__ bf16 g_pstTH[(size_t)BB * DD * SS];
__device__ bf16 g_pstTL[(size_t)BB * DD * SS];
__device__ bf16 g_preTH[(size_t)BB * DD * SS];
__device__ bf16 g_preTL[(size_t)BB * DD * SS];
__device__ bf16 g_gateH[(size_t)BB * SS * SS];
__device__ bf16 g_gateL[(size_t)BB * SS * SS];
__device__ bf16 g_W1tH[DD * DP];
__device__ bf16 g_W1tL[DD * DP];
__device__ bf16 g_W2tH[OUTD * DP];
__device__ bf16 g_W2tL[OUTD * DP];

// ---------------- helpers ----------------
__device__ __forceinline__ uint32_t smem_u32(const void* p) {
    uint32_t a;
    asm("{ .reg .u64 t; cvta.to.shared.u64 t, %1; cvt.u32.u64 %0, t; }" : "=r"(a) : "l"(p));
    return a;
}
__device__ __forceinline__ void cp16(uint32_t dst, const void* src, unsigned sz) {
    asm volatile("cp.async.cg.shared.global [%0], [%1], 16, %2;"
        :: "r"(dst), "l"(src), "r"(sz) : "memory");
}
#define CP_COMMIT() asm volatile("cp.async.commit_group;" ::: "memory")

__device__ __forceinline__ void ldm4(uint32_t* r, uint32_t addr) {
    asm volatile("ldmatrix.sync.aligned.m8n8.x4.shared.b16 {%0,%1,%2,%3}, [%4];"
        : "=r"(r[0]), "=r"(r[1]), "=r"(r[2]), "=r"(r[3]) : "r"(addr));
}
__device__ __forceinline__ void ldm2(uint32_t* r, uint32_t addr) {
    asm volatile("ldmatrix.sync.aligned.m8n8.x2.shared.b16 {%0,%1}, [%2];"
        : "=r"(r[0]), "=r"(r[1]) : "r"(addr));
}
__device__ __forceinline__ void mma16(float* d, const uint32_t* a, const uint32_t* b) {
    asm volatile("mma.sync.aligned.m16n8k16.row.col.f32.bf16.bf16.f32 "
        "{%0,%1,%2,%3}, {%4,%5,%6,%7}, {%8,%9}, {%0,%1,%2,%3};"
        : "+f"(d[0]), "+f"(d[1]), "+f"(d[2]), "+f"(d[3])
        : "r"(a[0]), "r"(a[1]), "r"(a[2]), "r"(a[3]), "r"(b[0]), "r"(b[1]));
}
__device__ __forceinline__ void bsplit(float v, bf16& h, bf16& l) {
    h = __float2bfloat16_rn(v);
    l = __float2bfloat16_rn(v - __bfloat162float(h));
}
__device__ __forceinline__ uint32_t bpack(bf16 a, bf16 b) {
    return (uint32_t)__bfloat16_as_ushort(a) | ((uint32_t)__bfloat16_as_ushort(b) << 16);
}

// ---------------- bf16x3 tensor-core GEMM ----------------
// C[M,N] = epi(A[M,K] @ B[N,K]^T), A/B given as bf16 hi/lo pairs, K % 32 == 0
// (K is the PADDED stride; pad region must be zero). M % 128 == 0.
// EPI: 0 none | 1 sigmoid | 2 +aux[r,c] | 3 relu(+bias) | 4 +bias
// OUT: 0 fp32 (Cf, stride N) | 1 split (Ch/Cl, stride ldC) | 2 both
static constexpr int SK = 40;                       // bf16 k-stride in smem (pad)
static constexpr int TILE_B = 128 * SK * 2;         // 10240 B per tile
static constexpr int STAGE_B = 4 * TILE_B;          // Ah, Al, Bh, Bl
static constexpr uint32_t MG_SMEM = 2 * STAGE_B;    // 81920 B

template <int EPI, int OUT>
__global__ void __launch_bounds__(256)
mgemm(const bf16* __restrict__ Ah_, const bf16* __restrict__ Al_,
      const bf16* __restrict__ Bh_, const bf16* __restrict__ Bl_,
      float* __restrict__ Cf, bf16* __restrict__ Ch, bf16* __restrict__ Cl,
      const float* __restrict__ aux,
      int M, int N, int K, int ldC, int ldAux,
      long long sA, long long sB, long long sCf, long long sCs, long long sAux)
{
    extern __shared__ char smem[];
    const uint32_t sm0 = smem_u32(smem);
    const int tid = threadIdx.x;
    const int wid = tid >> 5, lane = tid & 31;
    const int g = lane >> 2, tg = lane & 3;
    const int wr = wid >> 2, wc = wid & 3;
    const int rowTile = blockIdx.y * 128;
    const int colTile = blockIdx.x * 128;

    const bf16* Ah = Ah_ + (size_t)blockIdx.z * sA;
    const bf16* Al = Al_ + (size_t)blockIdx.z * sA;
    const bf16* Bh = Bh_ + (size_t)blockIdx.z * sB;
    const bf16* Bl = Bl_ + (size_t)blockIdx.z * sB;

    float acc[4][4][4];
#pragma unroll
    for (int i = 0; i < 4; i++)
#pragma unroll
        for (int j = 0; j < 4; j++)
#pragma unroll
            for (int t = 0; t < 4; t++) acc[i][j][t] = 0.0f;

    const int T = K >> 5;

    // loader mapping: thread -> (row, k-quarter)
    const int lrow = tid >> 1;
    const int lkq  = (tid & 1) * 16;
    const int bn   = colTile + lrow;
    const unsigned bsz = (bn < N) ? 16u : 0u;
    const int bnc  = (bn < N) ? bn : (N - 1);
    const uint32_t ldoff = (uint32_t)(lrow * SK + lkq) * 2;

    auto issue = [&](int t) {
        const uint32_t sb = sm0 + (uint32_t)(t & 1) * STAGE_B;
        const size_t gk = (size_t)(t << 5) + lkq;
        const bf16* pa = Ah + (size_t)(rowTile + lrow) * K + gk;
        cp16(sb + ldoff,      pa,     16);
        cp16(sb + ldoff + 16, pa + 8, 16);
        pa = Al + (size_t)(rowTile + lrow) * K + gk;
        cp16(sb + TILE_B + ldoff,      pa,     16);
        cp16(sb + TILE_B + ldoff + 16, pa + 8, 16);
        const bf16* pb = Bh + (size_t)bnc * K + gk;
        cp16(sb + 2 * TILE_B + ldoff,      pb,     bsz);
        cp16(sb + 2 * TILE_B + ldoff + 16, pb + 8, bsz);
        pb = Bl + (size_t)bnc * K + gk;
        cp16(sb + 3 * TILE_B + ldoff,      pb,     bsz);
        cp16(sb + 3 * TILE_B + ldoff + 16, pb + 8, bsz);
    };

    // ldmatrix lane-address components
    const uint32_t aoff = (uint32_t)(((wr * 64 + (lane & 7) + ((lane >> 3) & 1) * 8) * SK
                                      + ((lane >> 4) & 1) * 8) * 2);
    const uint32_t boff = (uint32_t)(((wc * 32 + (lane & 7)) * SK
                                      + ((lane >> 3) & 1) * 8) * 2);

    issue(0); CP_COMMIT();

    for (int t = 0; t < T; t++) {
        if (t + 1 < T) {
            issue(t + 1); CP_COMMIT();
            asm volatile("cp.async.wait_group 1;" ::: "memory");
        } else {
            asm volatile("cp.async.wait_group 0;" ::: "memory");
        }
        __syncthreads();

        const uint32_t sb = sm0 + (uint32_t)(t & 1) * STAGE_B;
#pragma unroll
        for (int ks = 0; ks < 2; ks++) {
            uint32_t ah[4][4], al[4][4], bh[4][2], bl[4][2];
#pragma unroll
            for (int mi = 0; mi < 4; mi++) {
                const uint32_t addr = sb + aoff + mi * (16 * SK * 2) + ks * 32;
                ldm4(ah[mi], addr);
                ldm4(al[mi], addr + TILE_B);
            }
#pragma unroll
            for (int nj = 0; nj < 4; nj++) {
                const uint32_t addr = sb + 2 * TILE_B + boff + nj * (8 * SK * 2) + ks * 32;
                ldm2(bh[nj], addr);
                ldm2(bl[nj], addr + TILE_B);
            }
#pragma unroll
            for (int mi = 0; mi < 4; mi++)
#pragma unroll
                for (int nj = 0; nj < 4; nj++) {
                    mma16(acc[mi][nj], ah[mi], bh[nj]);
                    mma16(acc[mi][nj], ah[mi], bl[nj]);
                    mma16(acc[mi][nj], al[mi], bh[nj]);
                }
        }
        __syncthreads();
    }

    // ---------------- epilogue ----------------
    float* Cfb = (OUT != 1) ? Cf + (size_t)blockIdx.z * sCf : (float*)0;
    bf16*  Chb = (OUT != 0) ? Ch + (size_t)blockIdx.z * sCs : (bf16*)0;
    bf16*  Clb = (OUT != 0) ? Cl + (size_t)blockIdx.z * sCs : (bf16*)0;
    const float* Xb = aux ? aux + (size_t)blockIdx.z * sAux : (const float*)0;

#pragma unroll
    for (int mi = 0; mi < 4; mi++) {
#pragma unroll
        for (int nj = 0; nj < 4; nj++) {
            const int c = colTile + wc * 32 + nj * 8 + tg * 2;
#pragma unroll
            for (int half = 0; half < 2; half++) {
                const int r = rowTile + wr * 64 + mi * 16 + g + half * 8;
                float v0 = acc[mi][nj][half * 2 + 0];
                float v1 = acc[mi][nj][half * 2 + 1];
                if (c < N) {
                    if (EPI == 1) {
                        v0 = 1.0f / (1.0f + __expf(-v0));
                        v1 = 1.0f / (1.0f + __expf(-v1));
                    } else if (EPI == 2) {
                        const float2 x2 = *(const float2*)&Xb[(size_t)r * ldAux + c];
                        v0 += x2.x; v1 += x2.y;
                    } else if (EPI == 3) {
                        const float2 b2 = *(const float2*)&Xb[c];
                        v0 = fmaxf(v0 + b2.x, 0.f);
                        v1 = fmaxf(v1 + b2.y, 0.f);
                    } else if (EPI == 4) {
                        const float2 b2 = *(const float2*)&Xb[c];
                        v0 += b2.x; v1 += b2.y;
                    }
                } else { v0 = 0.f; v1 = 0.f; }
                if (OUT != 1) {
                    if (c < N) *(float2*)&Cfb[(size_t)r * N + c] = make_float2(v0, v1);
                }
                if (OUT != 0) {
                    if (c < ldC) {
                        bf16 h0, l0, h1, l1;
                        bsplit(v0, h0, l0); bsplit(v1, h1, l1);
                        *(uint32_t*)&Chb[(size_t)r * ldC + c] = bpack(h0, h1);
                        *(uint32_t*)&Clb[(size_t)r * ldC + c] = bpack(l0, l1);
                    }
                }
            }
        }
    }
}

// ---------------- projection (fp32 out): C[M,300] = act(A[M,50] @ W + b) -------
__global__ void proj_kernel(const float* __restrict__ A, const float* __restrict__ W,
                            const float* __restrict__ bias, float* __restrict__ C,
                            int act)
{
    __shared__ float sA[32][DIN];
    const int j = threadIdx.x;
    const int row0 = blockIdx.x * 32;
    for (int i = threadIdx.x; i < 32 * DIN; i += blockDim.x)
        sA[i / DIN][i % DIN] = A[(size_t)(row0 + i / DIN) * DIN + (i % DIN)];
    __syncthreads();
    float w[DIN];
#pragma unroll
    for (int k = 0; k < DIN; k++) w[k] = W[k * DD + j];
    const float b = bias ? bias[j] : 0.0f;
#pragma unroll 4
    for (int r = 0; r < 32; r++) {
        float acc = b;
#pragma unroll
        for (int k = 0; k < DIN; k++) acc += sA[r][k] * w[k];
        if (act) acc = tanhf(acc);
        C[(size_t)(row0 + r) * DD + j] = acc;
    }
}

// ---------------- projection (split bf16 out, tanh, pad-zeroed) ----------------
__global__ void proj_split_kernel(const float* __restrict__ A, const float* __restrict__ W,
                                  const float* __restrict__ bias,
                                  bf16* __restrict__ oh, bf16* __restrict__ ol)
{
    __shared__ float sA[32][DIN];
    const int j = threadIdx.x;
    const int row0 = blockIdx.x * 32;
    for (int i = threadIdx.x; i < 32 * DIN; i += blockDim.x)
        sA[i / DIN][i % DIN] = A[(size_t)(row0 + i / DIN) * DIN + (i % DIN)];
    __syncthreads();
    float w[DIN];
#pragma unroll
    for (int k = 0; k < DIN; k++) w[k] = W[k * DD + j];
    const float b = bias[j];
#pragma unroll 4
    for (int r = 0; r < 32; r++) {
        float acc = b;
#pragma unroll
        for (int k = 0; k < DIN; k++) acc += sA[r][k] * w[k];
        acc = tanhf(acc);
        bf16 h, l;
        bsplit(acc, h, l);
        oh[(size_t)(row0 + r) * DP + j] = h;
        ol[(size_t)(row0 + r) * DP + j] = l;
    }
    if (j < DP - DD) {
        const bf16 z = __float2bfloat16_rn(0.f);
#pragma unroll 4
        for (int r = 0; r < 32; r++) {
            oh[(size_t)(row0 + r) * DP + DD + j] = z;
            ol[(size_t)(row0 + r) * DP + DD + j] = z;
        }
    }
}

// ---------------- LayerNorm over last dim (300), in place ---------------------
__global__ void ln_kernel(float* __restrict__ T,
                          const float* __restrict__ g, const float* __restrict__ b)
{
    const int row = blockIdx.x * (blockDim.x >> 5) + (threadIdx.x >> 5);
    const int lane = threadIdx.x & 31;
    float* p = T + (size_t)row * DD;
    float v[10];
    float s = 0.0f;
#pragma unroll
    for (int i = 0; i < 10; i++) {
        int j = lane + i * 32;
        v[i] = (j < DD) ? p[j] : 0.0f;
        s += v[i];
    }
#pragma unroll
    for (int o = 16; o; o >>= 1) s += __shfl_xor_sync(0xffffffffu, s, o);
    const float mu = s * (1.0f / DD);
    float q = 0.0f;
#pragma unroll
    for (int i = 0; i < 10; i++) {
        int j = lane + i * 32;
        if (j < DD) { float d = v[i] - mu; q += d * d; }
    }
#pragma unroll
    for (int o = 16; o; o >>= 1) q += __shfl_xor_sync(0xffffffffu, q, o);
    const float inv = rsqrtf(q * (1.0f / DD) + 1e-6f);
#pragma unroll
    for (int i = 0; i < 10; i++) {
        int j = lane + i * 32;
        if (j < DD) p[j] = g[j] * (v[i] - mu) * inv + b[j];
    }
}

// ---------- split-transpose: out[c][r] (bf16 hi/lo, [C][Rpad]) = in[r][c] ------
__global__ void split_transpose(const float* __restrict__ in,
                                bf16* __restrict__ oh, bf16* __restrict__ ol,
                                int R, int Rpad, int C,
                                long long sIn, long long sOut)
{
    __shared__ float t[32][33];
    const float* ib = in + (size_t)blockIdx.z * sIn;
    bf16* ohb = oh + (size_t)blockIdx.z * sOut;
    bf16* olb = ol + (size_t)blockIdx.z * sOut;
    const int r0 = blockIdx.x * 32;   // over Rpad
    const int c0 = blockIdx.y * 32;   // over C
    const int x = threadIdx.x, y = threadIdx.y;
#pragma unroll
    for (int i = 0; i < 32; i += 8) {
        int r = r0 + y + i, c = c0 + x;
        t[y + i][x] = (r < R && c < C) ? ib[(size_t)r * C + c] : 0.f;
    }
    __syncthreads();
#pragma unroll
    for (int i = 0; i < 32; i += 8) {
        int orow = c0 + y + i, ocol = r0 + x;
        if (orow < C && ocol < Rpad) {
            bf16 h, l;
            bsplit(t[x][y + i], h, l);
            ohb[(size_t)orow * Rpad + ocol] = h;
            olb[(size_t)orow * Rpad + ocol] = l;
        }
    }
}

// -------------------------------------------------------------------------------
extern "C" void kernel_launch(void* const* d_in, const int* in_sizes, int n_in,
                              void* d_out, int out_size)
{
    (void)in_sizes; (void)n_in; (void)out_size;

    const float* x    = (const float*)d_in[0];
    const float* ME   = (const float*)d_in[1];
    const float* past = (const float*)d_in[2];
    const float* w_pt = (const float*)d_in[3];
    const float* b_pt = (const float*)d_in[4];
    const float* w_pg = (const float*)d_in[5];
    const float* b_pg = (const float*)d_in[6];
    const float* w_ps = (const float*)d_in[7];
    const float* b_ps = (const float*)d_in[8];
    const float* w_ex = (const float*)d_in[9];
    const float* b_ex = (const float*)d_in[10];
    const float* ln_g = (const float*)d_in[11];
    const float* ln_b = (const float*)d_in[12];
    const float* W1   = (const float*)d_in[13];
    const float* b1   = (const float*)d_in[14];
    const float* W2   = (const float*)d_in[15];
    const float* b2   = (const float*)d_in[16];
    float* out = (float*)d_out;

    float *p_token, *p_pst, *p_pre;
    bf16 *ptokH, *ptokL, *pvecH, *pvecL, *expH, *expL, *preH, *preL;
    bf16 *filtH, *filtL, *hH, *hL, *pstTH, *pstTL, *preTH, *preTL;
    bf16 *gateH, *gateL, *W1tH, *W1tL, *W2tH, *W2tL;
    cudaGetSymbolAddress((void**)&p_token, g_token);
    cudaGetSymbolAddress((void**)&p_pst,   g_pst);
    cudaGetSymbolAddress((void**)&p_pre,   g_pre);
    cudaGetSymbolAddress((void**)&ptokH, g_ptokH); cudaGetSymbolAddress((void**)&ptokL, g_ptokL);
    cudaGetSymbolAddress((void**)&pvecH, g_pvecH); cudaGetSymbolAddress((void**)&pvecL, g_pvecL);
    cudaGetSymbolAddress((void**)&expH,  g_expH);  cudaGetSymbolAddress((void**)&expL,  g_expL);
    cudaGetSymbolAddress((void**)&preH,  g_preH);  cudaGetSymbolAddress((void**)&preL,  g_preL);
    cudaGetSymbolAddress((void**)&filtH, g_filtH); cudaGetSymbolAddress((void**)&filtL, g_filtL);
    cudaGetSymbolAddress((void**)&hH,    g_hH);    cudaGetSymbolAddress((void**)&hL,    g_hL);
    cudaGetSymbolAddress((void**)&pstTH, g_pstTH); cudaGetSymbolAddress((void**)&pstTL, g_pstTL);
    cudaGetSymbolAddress((void**)&preTH, g_preTH); cudaGetSymbolAddress((void**)&preTL, g_preTL);
    cudaGetSymbolAddress((void**)&gateH, g_gateH); cudaGetSymbolAddress((void**)&gateL, g_gateL);
    cudaGetSymbolAddress((void**)&W1tH,  g_W1tH);  cudaGetSymbolAddress((void**)&W1tL,  g_W1tL);
    cudaGetSymbolAddress((void**)&W2tH,  g_W2tH);  cudaGetSymbolAddress((void**)&W2tL,  g_W2tL);

    cudaFuncSetAttribute(mgemm<1,1>, cudaFuncAttributeMaxDynamicSharedMemorySize, MG_SMEM);
    cudaFuncSetAttribute(mgemm<0,2>, cudaFuncAttributeMaxDynamicSharedMemorySize, MG_SMEM);
    cudaFuncSetAttribute(mgemm<2,1>, cudaFuncAttributeMaxDynamicSharedMemorySize, MG_SMEM);
    cudaFuncSetAttribute(mgemm<3,1>, cudaFuncAttributeMaxDynamicSharedMemorySize, MG_SMEM);
    cudaFuncSetAttribute(mgemm<4,0>, cudaFuncAttributeMaxDynamicSharedMemorySize, MG_SMEM);

    const long long sDf = (long long)SS * DD;     // fp32 per-batch [1024,300]
    const long long sDp = (long long)SS * DP;     // split per-batch [1024,320]
    const long long sTT = (long long)DD * SS;     // [300,1024]
    const long long sG  = (long long)SS * SS;     // [1024,1024]
    dim3 tpb(32, 8);

    // projections (K = 50, FFMA path)
    proj_kernel<<<NBS / 32, 300>>>(x,    ME,   (const float*)0, p_token, 0);
    proj_kernel<<<NBS / 32, 300>>>(past, w_ps, b_ps, p_pst, 1);
    proj_split_kernel<<<NBS / 32, 300>>>(x,    w_pt, b_pt, ptokH, ptokL);
    proj_split_kernel<<<NBS / 32, 300>>>(x,    w_ex, b_ex, expH,  expL);
    proj_split_kernel<<<NBS / 32, 300>>>(past, w_pg, b_pg, pvecH, pvecL);
    ln_kernel<<<NBS / 8, 256>>>(p_token, ln_g, ln_b);

    // transposed split operands
    split_transpose<<<dim3(32, 10, BB), tpb>>>(p_pst, pstTH, pstTL, SS, SS, DD, sDf, sTT);
    split_transpose<<<dim3(10, 10, 1),  tpb>>>(W1, W1tH, W1tL, DD, DP, DD, 0, 0);
    split_transpose<<<dim3(10, 32, 1),  tpb>>>(W2, W2tH, W2tL, DD, DP, OUTD, 0, 0);

    // G1: gate = sigmoid(ptok @ pvec^T)   -> split bf16
    mgemm<1,1><<<dim3(8, 8, BB), 256, MG_SMEM>>>(
        ptokH, ptokL, pvecH, pvecL, (float*)0, gateH, gateL, (const float*)0,
        SS, SS, DP, SS, 0, sDp, sDp, 0, sG, 0);

    // G2: pre = gate @ past_state  -> fp32 + split bf16 (row-major)
    mgemm<0,2><<<dim3(3, 8, BB), 256, MG_SMEM>>>(
        gateH, gateL, pstTH, pstTL, p_pre, preH, preL, (const float*)0,
        SS, DD, SS, DP, 0, sG, sTT, sDf, sDp, 0);

    // preT split
    split_transpose<<<dim3(32, 10, BB), tpb>>>(p_pre, preTH, preTL, SS, SS, DD, sDf, sTT);

    // G3: gate2 = sigmoid(exp @ pre^T)   -> split bf16 (reuse gate buffers)
    mgemm<1,1><<<dim3(8, 8, BB), 256, MG_SMEM>>>(
        expH, expL, preH, preL, (float*)0, gateH, gateL, (const float*)0,
        SS, SS, DP, SS, 0, sDp, sDp, 0, sG, 0);

    // G4: filter = token + gate2 @ pre  -> split bf16
    mgemm<2,1><<<dim3(3, 8, BB), 256, MG_SMEM>>>(
        gateH, gateL, preTH, preTL, (float*)0, filtH, filtL, p_token,
        SS, DD, SS, DP, DD, sG, sTT, 0, sDp, sDf);

    // G5: h = relu(filter @ W1 + b1)  -> split bf16
    mgemm<3,1><<<dim3(3, 512, 1), 256, MG_SMEM>>>(
        filtH, filtL, W1tH, W1tL, (float*)0, hH, hL, b1,
        NBS, DD, DP, DP, 0, 0, 0, 0, 0, 0);

    // G6: out = h @ W2 + b2  -> fp32
    mgemm<4,0><<<dim3(8, 512, 1), 256, MG_SMEM>>>(
        hH, hL, W2tH, W2tL, out, (bf16*)0, (bf16*)0, b2,
        NBS, OUTD, DP, OUTD, 0, 0, 0, 0, 0, 0);
}